// round 14
// baseline (speedup 1.0000x reference)
#include <cuda_runtime.h>
#include <cuda_bf16.h>
#include <math.h>
#include <stdint.h>

#define B_   2
#define S_   2048
#define E_   1024
#define NH_  16
#define NKV_ 4
#define HD_  64
#define GATE_CH_ 12
#define TOKENS (B_ * S_)   // 4096

// ---------------------------------------------------------------------------
// Scratch (device globals: no allocation allowed)
// ---------------------------------------------------------------------------
__device__ float g_qkv[TOKENS * 1536];   // fused QKV output; later reused as y[4096x1024]

__device__ __nv_bfloat16 g_qh[TOKENS * NH_ * HD_];
__device__ __nv_bfloat16 g_ql[TOKENS * NH_ * HD_];
__device__ __nv_bfloat16 g_kh[TOKENS * NKV_ * HD_];
__device__ __nv_bfloat16 g_kl[TOKENS * NKV_ * HD_];
__device__ __nv_bfloat16 g_vh[TOKENS * NKV_ * HD_];
__device__ __nv_bfloat16 g_vl[TOKENS * NKV_ * HD_];

// int8 balanced fixed-point split (value = s_row * (Q1*128 + Q2), Q2 centered)
__device__ int8_t g_x1[TOKENS * E_];
__device__ int8_t g_x2[TOKENS * E_];
__device__ float  g_xs[TOKENS];
// weight rows: [Wq 0..1024 | Wk 1024..1280 | Wv 1280..1536 | Wproj 1536..2560]
#define WP_OFF (1536 * E_)
__device__ int8_t g_w1[2560 * E_];
__device__ int8_t g_w2[2560 * E_];
__device__ float  g_ws[2560];
__device__ int8_t g_y1[TOKENS * E_];
__device__ int8_t g_y2[TOKENS * E_];
__device__ float  g_ys[TOKENS];

// ---------------------------------------------------------------------------
// PTX helpers
// ---------------------------------------------------------------------------
__device__ __forceinline__ void ldsm4(uint32_t* r, uint32_t addr)
{
    asm volatile("ldmatrix.sync.aligned.m8n8.x4.shared.b16 {%0,%1,%2,%3}, [%4];"
                 : "=r"(r[0]), "=r"(r[1]), "=r"(r[2]), "=r"(r[3]) : "r"(addr));
}
__device__ __forceinline__ void ldsm4t(uint32_t* r, uint32_t addr)
{
    asm volatile("ldmatrix.sync.aligned.m8n8.x4.trans.shared.b16 {%0,%1,%2,%3}, [%4];"
                 : "=r"(r[0]), "=r"(r[1]), "=r"(r[2]), "=r"(r[3]) : "r"(addr));
}
__device__ __forceinline__ void mma16816(float* c, const uint32_t* a, const uint32_t* b)
{
    asm volatile(
        "mma.sync.aligned.m16n8k16.row.col.f32.bf16.bf16.f32 "
        "{%0,%1,%2,%3},{%4,%5,%6,%7},{%8,%9},{%0,%1,%2,%3};"
        : "+f"(c[0]), "+f"(c[1]), "+f"(c[2]), "+f"(c[3])
        : "r"(a[0]), "r"(a[1]), "r"(a[2]), "r"(a[3]), "r"(b[0]), "r"(b[1]));
}
// int8 IMMA: K=32 per instruction (half the instruction count of bf16 k16)
__device__ __forceinline__ void mma16832s8(int* c, const uint32_t* a, const uint32_t* b)
{
    asm volatile(
        "mma.sync.aligned.m16n8k32.row.col.s32.s8.s8.s32 "
        "{%0,%1,%2,%3},{%4,%5,%6,%7},{%8,%9},{%0,%1,%2,%3};"
        : "+r"(c[0]), "+r"(c[1]), "+r"(c[2]), "+r"(c[3])
        : "r"(a[0]), "r"(a[1]), "r"(a[2]), "r"(a[3]), "r"(b[0]), "r"(b[1]));
}
__device__ __forceinline__ void cpasync16(uint32_t s, const void* g)
{
    asm volatile("cp.async.cg.shared.global [%0], [%1], 16;" :: "r"(s), "l"(g));
}
__device__ __forceinline__ void cpcommit() { asm volatile("cp.async.commit_group;"); }
template<int N> __device__ __forceinline__ void cpwait()
{ asm volatile("cp.async.wait_group %0;" :: "n"(N)); }

__device__ __forceinline__ uint32_t packbf2(float a, float b)
{
    __nv_bfloat162 t = __floats2bfloat162_rn(a, b);
    uint32_t u; memcpy(&u, &t, 4); return u;
}

// ---------------------------------------------------------------------------
// Row quantization: balanced 15-bit split. value = s*(A1*128 + A2),
// A1 = (a+64)>>7 in [-127,127], A2 = a - A1*128 in [-64,63] (zero-mean).
// Dropped S22 cross-term is now unbiased (~6e-5 relative).
// ---------------------------------------------------------------------------
__device__ __forceinline__ void quant_row_body(
    const float* __restrict__ src, int8_t* __restrict__ q1row,
    int8_t* __restrict__ q2row, float* __restrict__ scl_slot, int tid)
{
    __shared__ float red[8];
    float4 v = ((const float4*)src)[tid];
    float vv[4] = {v.x, v.y, v.z, v.w};
    float m = fmaxf(fmaxf(fabsf(vv[0]), fabsf(vv[1])),
                    fmaxf(fabsf(vv[2]), fabsf(vv[3])));
#pragma unroll
    for (int o = 16; o > 0; o >>= 1)
        m = fmaxf(m, __shfl_xor_sync(0xffffffffu, m, o));
    if ((tid & 31) == 0) red[tid >> 5] = m;
    __syncthreads();
    float mm = fmaxf(fmaxf(fmaxf(red[0], red[1]), fmaxf(red[2], red[3])),
                     fmaxf(fmaxf(red[4], red[5]), fmaxf(red[6], red[7])));
    mm = fmaxf(mm, 1e-20f);
    float inv = 16256.f / mm;
    if (tid == 0) *scl_slot = mm / 16256.f;

    int q1[4], q2[4];
#pragma unroll
    for (int j = 0; j < 4; j++) {
        int a = __float2int_rn(vv[j] * inv);   // |a| <= 16256
        int a1 = (a + 64) >> 7;                // nearest, in [-127, 127]
        int a2 = a - (a1 << 7);                // in [-64, 63]
        q1[j] = a1; q2[j] = a2;
    }
    uint32_t p1 = (q1[0] & 255) | ((q1[1] & 255) << 8) |
                  ((q1[2] & 255) << 16) | ((uint32_t)(q1[3] & 255) << 24);
    uint32_t p2 = (q2[0] & 255) | ((q2[1] & 255) << 8) |
                  ((q2[2] & 255) << 16) | ((uint32_t)(q2[3] & 255) << 24);
    ((uint32_t*)q1row)[tid] = p1;
    ((uint32_t*)q2row)[tid] = p2;
}

__global__ __launch_bounds__(256)
void quant_rows(const float* __restrict__ in, int8_t* __restrict__ q1,
                int8_t* __restrict__ q2, float* __restrict__ scl)
{
    int row = blockIdx.x;
    quant_row_body(in + (size_t)row * E_,
                   q1 + (size_t)row * E_, q2 + (size_t)row * E_,
                   scl + row, threadIdx.x);
}

__global__ __launch_bounds__(256)
void quantw_kernel(const float* __restrict__ Wq, const float* __restrict__ Wk,
                   const float* __restrict__ Wv, const float* __restrict__ Wp)
{
    int row = blockIdx.x;
    const float* src;
    if      (row < 1024) src = Wq + (size_t)row * E_;
    else if (row < 1280) src = Wk + (size_t)(row - 1024) * E_;
    else if (row < 1536) src = Wv + (size_t)(row - 1280) * E_;
    else                 src = Wp + (size_t)(row - 1536) * E_;
    quant_row_body(src, g_w1 + (size_t)row * E_, g_w2 + (size_t)row * E_,
                   g_ws + row, threadIdx.x);
}

// ---------------------------------------------------------------------------
// int8 IMMA GEMM: C[M,N] = (sa.(A1*128+A2)) @ (sb.(B1*128+B2))^T
//   = sa_i*sb_j*(16384*S11 + 128*(S12+S21))  [S22 zero-mean, dropped]
// tile 128x128, K-chunk 64 int8/row (128B = [Q1 k0..63 | Q2 k0..63]),
// XOR-(row&7) 16B-chunk swizzle; s8-k32 fragments positionally = f16-k16.
// 3-stage cp.async ring, one __syncthreads per k-iter. 256 threads.
// ---------------------------------------------------------------------------
#define GS_STG  32768
#define GS_SMEM (3 * GS_STG)   // 96 KB

__global__ __launch_bounds__(256, 1)
void gemm_s8(const int8_t* __restrict__ A1, const int8_t* __restrict__ A2,
             const float* __restrict__ sA,
             const int8_t* __restrict__ B1, const int8_t* __restrict__ B2,
             const float* __restrict__ sB,
             float* __restrict__ C, int ldc, int K)
{
    extern __shared__ __align__(16) unsigned char gsm[];
    const uint32_t smBase = (uint32_t)__cvta_generic_to_shared(gsm);

    const int tid  = threadIdx.x;
    const int lane = tid & 31;
    const int warp = tid >> 5;
    const int wm = warp >> 2;          // 0..1 -> 64 rows
    const int wn = warp & 3;           // 0..3 -> 32 cols
    const int bm = blockIdx.y * 128;
    const int bn = blockIdx.x * 128;

    const int lchunk = tid & 7;        // data chunk: 0-3 = Q1, 4-7 = Q2
    const int lrow0  = tid >> 3;
    const int8_t* Asrc = (lchunk < 4) ? A1 : A2;
    const int8_t* Bsrc = (lchunk < 4) ? B1 : B2;
    const int kcol = (lchunk & 3) * 16;    // 16 int8 per 16B chunk

    const int niter = K >> 6;          // 64 int8 per iter

    auto issue_stage = [&](int it) {
        uint32_t base = smBase + (it % 3) * GS_STG;
        int k0 = it * 64;
#pragma unroll
        for (int r = 0; r < 4; r++) {
            int row = lrow0 + r * 32;
            uint32_t so = row * 128 + ((lchunk ^ (row & 7)) * 16);
            cpasync16(base + so,
                      Asrc + (size_t)(bm + row) * K + k0 + kcol);
            cpasync16(base + 16384 + so,
                      Bsrc + (size_t)(bn + row) * K + k0 + kcol);
        }
    };

    issue_stage(0); cpcommit();
    issue_stage(1); cpcommit();

    int accH[4][4][4], accM[4][4][4];
#pragma unroll
    for (int i = 0; i < 4; i++)
#pragma unroll
        for (int j = 0; j < 4; j++)
#pragma unroll
            for (int r = 0; r < 4; r++) { accH[i][j][r] = 0; accM[i][j][r] = 0; }

    const int a_r = lane & 15;
    const int a_c = (lane >> 4) & 1;
    const int b_r = ((lane >> 4) & 1) * 8 + (lane & 7);
    const int b_c = (lane >> 3) & 1;

    for (int i = 0; i < niter; i++) {
        cpwait<1>();
        __syncthreads();
        if (i + 2 < niter) issue_stage(i + 2);
        cpcommit();

        const uint32_t aB = smBase + (i % 3) * GS_STG;
        const uint32_t wB = aB + 16384;

#pragma unroll
        for (int kk = 0; kk < 2; kk++) {   // each kk = K=32 int8
            uint32_t a1[4][4], b1[4][2];
            // phase 1: A1, B1 -> accH += A1*B1
#pragma unroll
            for (int mf = 0; mf < 4; mf++) {
                int R = wm * 64 + mf * 16 + a_r;
                int chi = kk * 2 + a_c;
                ldsm4(a1[mf], aB + R * 128 + ((chi ^ (R & 7)) * 16));
            }
#pragma unroll
            for (int np = 0; np < 2; np++) {
                int R = wn * 32 + np * 16 + b_r;
                int chi = kk * 2 + b_c;
                uint32_t t[4];
                ldsm4(t, wB + R * 128 + ((chi ^ (R & 7)) * 16));
                b1[2 * np][0] = t[0]; b1[2 * np][1] = t[1];
                b1[2 * np + 1][0] = t[2]; b1[2 * np + 1][1] = t[3];
            }
#pragma unroll
            for (int mf = 0; mf < 4; mf++)
#pragma unroll
                for (int nf = 0; nf < 4; nf++)
                    mma16832s8(accH[mf][nf], a1[mf], b1[nf]);

            // phase 2: B2 -> accM += A1*B2
            uint32_t b2[4][2];
#pragma unroll
            for (int np = 0; np < 2; np++) {
                int R = wn * 32 + np * 16 + b_r;
                int chi = kk * 2 + b_c;
                uint32_t t[4];
                ldsm4(t, wB + R * 128 + (((chi + 4) ^ (R & 7)) * 16));
                b2[2 * np][0] = t[0]; b2[2 * np][1] = t[1];
                b2[2 * np + 1][0] = t[2]; b2[2 * np + 1][1] = t[3];
            }
#pragma unroll
            for (int mf = 0; mf < 4; mf++)
#pragma unroll
                for (int nf = 0; nf < 4; nf++)
                    mma16832s8(accM[mf][nf], a1[mf], b2[nf]);

            // phase 3: A2 (reuse a1 regs) -> accM += A2*B1
#pragma unroll
            for (int mf = 0; mf < 4; mf++) {
                int R = wm * 64 + mf * 16 + a_r;
                int chi = kk * 2 + a_c;
                ldsm4(a1[mf], aB + R * 128 + (((chi + 4) ^ (R & 7)) * 16));
            }
#pragma unroll
            for (int mf = 0; mf < 4; mf++)
#pragma unroll
                for (int nf = 0; nf < 4; nf++)
                    mma16832s8(accM[mf][nf], a1[mf], b1[nf]);
        }
    }

    // epilogue: C = sa*sb*(16384*accH + 128*accM)
#pragma unroll
    for (int mf = 0; mf < 4; mf++) {
        int row0 = bm + wm * 64 + mf * 16 + (lane >> 2);
        float sa0 = sA[row0], sa1 = sA[row0 + 8];
#pragma unroll
        for (int nf = 0; nf < 4; nf++) {
            int col = bn + wn * 32 + nf * 8 + (lane & 3) * 2;
            float sb0 = sB[col], sb1 = sB[col + 1];
            int* h = accH[mf][nf];
            int* m = accM[mf][nf];
            float f0 = fmaf(16384.f, (float)h[0], 128.f * (float)m[0]);
            float f1 = fmaf(16384.f, (float)h[1], 128.f * (float)m[1]);
            float f2 = fmaf(16384.f, (float)h[2], 128.f * (float)m[2]);
            float f3 = fmaf(16384.f, (float)h[3], 128.f * (float)m[3]);
            *(float2*)(C + (size_t)row0 * ldc + col) =
                make_float2(sa0 * sb0 * f0, sa0 * sb1 * f1);
            *(float2*)(C + (size_t)(row0 + 8) * ldc + col) =
                make_float2(sa1 * sb0 * f2, sa1 * sb1 * f3);
        }
    }
}

// ---------------------------------------------------------------------------
// Elementwise: gate+ve on V, rope+rmsnorm(*1.2) on Q,K; reads fused g_qkv,
// emits bf16 hi/lo.
// ---------------------------------------------------------------------------
__global__ __launch_bounds__(256)
void ew_kernel(const float* __restrict__ x,
               const float* __restrict__ ve,
               const float* __restrict__ cosb,
               const float* __restrict__ sinb,
               const float* __restrict__ Wgate)
{
    const int token = blockIdx.x;
    const int s = token % S_;
    const int tid = threadIdx.x;

    __shared__ float gate_s[NKV_];
    __shared__ float cs[32], sn[32];

    if (tid < 32) {
        cs[tid] = cosb[s * 32 + tid];
        sn[tid] = sinb[s * 32 + tid];
    }
    if (tid >= 32 && tid < 32 + NKV_) {
        int kv = tid - 32;
        float acc = 0.f;
#pragma unroll
        for (int c = 0; c < GATE_CH_; c++)
            acc += x[(size_t)token * E_ + c] * Wgate[kv * GATE_CH_ + c];
        gate_s[kv] = 3.f / (1.f + expf(-acc));
    }
    __syncthreads();

    {   // v = v + gate*ve, split
        int kv = tid >> 6;
        float g = gate_s[kv];
        float v = g_qkv[(size_t)token * 1536 + 1280 + tid] + g * ve[(size_t)token * 256 + tid];
        size_t idx = (size_t)token * (NKV_ * HD_) + tid;
        __nv_bfloat16 h = __float2bfloat16(v);
        g_vh[idx] = h;
        g_vl[idx] = __float2bfloat16(v - __bfloat162float(h));
    }

    const int warp = tid >> 5, lane = tid & 31;
    const float c = cs[lane], si = sn[lane];

    for (int hh = warp; hh < NH_ + NKV_; hh += 8) {
        const float* base;
        __nv_bfloat16 *oh, *ol;
        if (hh < NH_) {
            base = g_qkv + (size_t)token * 1536 + hh * HD_;
            size_t off = (size_t)token * (NH_ * HD_) + hh * HD_;
            oh = g_qh + off; ol = g_ql + off;
        } else {
            int kv = hh - NH_;
            base = g_qkv + (size_t)token * 1536 + 1024 + kv * HD_;
            size_t off = (size_t)token * (NKV_ * HD_) + kv * HD_;
            oh = g_kh + off; ol = g_kl + off;
        }

        float x1 = base[lane];
        float x2 = base[lane + 32];
        float o1 =  x1 * c  + x2 * si;
        float o2 = -x1 * si + x2 * c;

        float ss = o1 * o1 + o2 * o2;
#pragma unroll
        for (int o = 16; o > 0; o >>= 1)
            ss += __shfl_xor_sync(0xffffffffu, ss, o);
        float r = rsqrtf(ss * (1.f / HD_) + 1.1920929e-7f) * 1.2f;
        float r1 = o1 * r, r2 = o2 * r;
        __nv_bfloat16 h1 = __float2bfloat16(r1);
        __nv_bfloat16 h2 = __float2bfloat16(r2);
        oh[lane]      = h1;
        oh[lane + 32] = h2;
        ol[lane]      = __float2bfloat16(r1 - __bfloat162float(h1));
        ol[lane + 32] = __float2bfloat16(r2 - __bfloat162float(h2));
    }
}

// ---------------------------------------------------------------------------
// Tensor-core flash attention (verified R9). 128 q-rows/block, 8 warps,
// 64-key tiles, split-bf16 3-term mma, 3-stage K/V ring.
// Epilogue writes fp32 y (proj is int8-quantized downstream).
// ---------------------------------------------------------------------------
#define ASMQ_L 16384
#define ASMKV  32768
#define ASTG   32768
#define ATT_SMEM (ASMKV + 3 * ASTG)   // 128 KB

__global__ void __launch_bounds__(256, 1) attn_mma_kernel()
{
    extern __shared__ __align__(16) unsigned char sm[];
    const int qt = (int)gridDim.x - 1 - (int)blockIdx.x;  // longest-first
    const int bh = blockIdx.y;
    const int b = bh / NH_, h = bh % NH_;
    const int kvh = h >> 2;

    const int tid = threadIdx.x;
    const int lane = tid & 31;
    const int warp = tid >> 5;          // 0..7

    const uint32_t smBase = (uint32_t)__cvta_generic_to_shared(sm);

    const int chunk = tid & 7;
    const int row0  = tid >> 3;         // 0..31

    // ---- load Q (hi/lo), 128 rows, swizzled ----
#pragma unroll
    for (int it = 0; it < 4; it++) {
        int row = row0 + it * 32;
        size_t g = ((size_t)(b * S_ + qt * 128 + row) * NH_ + h) * HD_ + chunk * 8;
        uint32_t so = row * 128 + ((chunk ^ (row & 7)) * 16);
        *(uint4*)(sm + so)          = *(const uint4*)(g_qh + g);
        *(uint4*)(sm + ASMQ_L + so) = *(const uint4*)(g_ql + g);
    }

    auto issue_kv = [&](int t) {
        uint32_t stg = smBase + ASMKV + (t % 3) * ASTG;
#pragma unroll
        for (int it = 0; it < 2; it++) {
            int row = row0 + it * 32;
            size_t g = ((size_t)(b * S_ + t * 64 + row) * NKV_ + kvh) * HD_ + chunk * 8;
            uint32_t so = row * 128 + ((chunk ^ (row & 7)) * 16);
            cpasync16(stg + so,         g_kh + g);
            cpasync16(stg + 8192 + so,  g_kl + g);
            cpasync16(stg + 16384 + so, g_vh + g);
            cpasync16(stg + 24576 + so, g_vl + g);
        }
        cpcommit();
    };

    const int tmax = 2 * qt + 1;
    issue_kv(0);
    if (tmax >= 1) issue_kv(1);

    __syncthreads();   // Q ready

    // ---- Q fragments ----
    const int a_r = lane & 15;
    const int a_c = (lane >> 4) & 1;
    uint32_t qfh[4][4], qfl[4][4];
    {
        int R = warp * 16 + a_r;
#pragma unroll
        for (int ks = 0; ks < 4; ks++) {
            int chi = ks * 2 + a_c;
            ldsm4(qfh[ks], smBase + R * 128 + ((chi ^ (R & 7)) * 16));
            ldsm4(qfl[ks], smBase + ASMQ_L + R * 128 + ((chi ^ (R & 7)) * 16));
        }
    }

    const int b_r = ((lane >> 4) & 1) * 8 + (lane & 7);
    const int b_c = (lane >> 3) & 1;
    const int t_grp = lane >> 3, t_off = lane & 7;
    const int tkey = ((t_grp & 1) * 8) + t_off;
    const int tnc  = t_grp >> 1;

    float yacc[8][4];
#pragma unroll
    for (int nf = 0; nf < 8; nf++)
#pragma unroll
        for (int r = 0; r < 4; r++) yacc[nf][r] = 0.f;
    float m0 = -INFINITY, m1 = -INFINITY, l0 = 0.f, l1 = 0.f;

    const float c2 = 0.125f * 1.44269504f;   // scale * log2(e)
    const int r0q = qt * 128 + warp * 16 + (lane >> 2);
    const int warp_last = qt * 128 + warp * 16 + 15;

    for (int t = 0; t <= tmax; t++) {
        if (t + 1 <= tmax) cpwait<1>();
        else               cpwait<0>();
        __syncthreads();   // everyone done reading stage (t-1)%3; stage t ready
        if (t + 2 <= tmax) issue_kv(t + 2);   // safe: fills (t-1)%3 post-barrier

        const bool skip = warp_last < t * 64;
        if (!skip) {
            const uint32_t sK  = smBase + ASMKV + (t % 3) * ASTG;
            const uint32_t sKl = sK + 8192;
            const uint32_t sV  = sK + 16384;
            const uint32_t sVl = sK + 24576;

            // ---- S = Q K^T ----
            float s[8][4];
#pragma unroll
            for (int nf = 0; nf < 8; nf++)
#pragma unroll
                for (int r = 0; r < 4; r++) s[nf][r] = 0.f;

#pragma unroll
            for (int ks = 0; ks < 4; ks++) {
                uint32_t kbh[8][2], kbl[8][2];
#pragma unroll
                for (int np = 0; np < 4; np++) {
                    int R = np * 16 + b_r;
                    int chi = ks * 2 + b_c;
                    uint32_t tt[4];
                    ldsm4(tt, sK + R * 128 + ((chi ^ (R & 7)) * 16));
                    kbh[2 * np][0] = tt[0]; kbh[2 * np][1] = tt[1];
                    kbh[2 * np + 1][0] = tt[2]; kbh[2 * np + 1][1] = tt[3];
                    ldsm4(tt, sKl + R * 128 + ((chi ^ (R & 7)) * 16));
                    kbl[2 * np][0] = tt[0]; kbl[2 * np][1] = tt[1];
                    kbl[2 * np + 1][0] = tt[2]; kbl[2 * np + 1][1] = tt[3];
                }
#pragma unroll
                for (int nf = 0; nf < 8; nf++) {
                    mma16816(s[nf], qfh[ks], kbh[nf]);
                    mma16816(s[nf], qfh[ks], kbl[nf]);
                    mma16816(s[nf], qfl[ks], kbh[nf]);
                }
            }

            // ---- causal mask (only possible on last two tiles) ----
            if (t >= 2 * qt) {
#pragma unroll
                for (int nf = 0; nf < 8; nf++) {
                    int c0 = t * 64 + nf * 8 + (lane & 3) * 2;
                    if (c0 > r0q)          s[nf][0] = -INFINITY;
                    if (c0 + 1 > r0q)      s[nf][1] = -INFINITY;
                    if (c0 > r0q + 8)      s[nf][2] = -INFINITY;
                    if (c0 + 1 > r0q + 8)  s[nf][3] = -INFINITY;
                }
            }

            // ---- online softmax (base-2) ----
            float tm0 = -INFINITY, tm1 = -INFINITY;
#pragma unroll
            for (int nf = 0; nf < 8; nf++) {
                tm0 = fmaxf(tm0, fmaxf(s[nf][0], s[nf][1]));
                tm1 = fmaxf(tm1, fmaxf(s[nf][2], s[nf][3]));
            }
            tm0 = fmaxf(tm0, __shfl_xor_sync(0xffffffffu, tm0, 1));
            tm0 = fmaxf(tm0, __shfl_xor_sync(0xffffffffu, tm0, 2));
            tm1 = fmaxf(tm1, __shfl_xor_sync(0xffffffffu, tm1, 1));
            tm1 = fmaxf(tm1, __shfl_xor_sync(0xffffffffu, tm1, 2));

            float mn0 = fmaxf(m0, tm0), mn1 = fmaxf(m1, tm1);
            float mb0 = mn0 * c2, mb1 = mn1 * c2;
            float cr0 = exp2f(m0 * c2 - mb0);
            float cr1 = exp2f(m1 * c2 - mb1);
            l0 *= cr0; l1 *= cr1;
#pragma unroll
            for (int nf = 0; nf < 8; nf++) {
                yacc[nf][0] *= cr0; yacc[nf][1] *= cr0;
                yacc[nf][2] *= cr1; yacc[nf][3] *= cr1;
            }
#pragma unroll
            for (int nf = 0; nf < 8; nf++) {
                s[nf][0] = exp2f(fmaf(s[nf][0], c2, -mb0));
                s[nf][1] = exp2f(fmaf(s[nf][1], c2, -mb0));
                s[nf][2] = exp2f(fmaf(s[nf][2], c2, -mb1));
                s[nf][3] = exp2f(fmaf(s[nf][3], c2, -mb1));
                l0 += s[nf][0] + s[nf][1];
                l1 += s[nf][2] + s[nf][3];
            }
            m0 = mn0; m1 = mn1;

            // ---- y += P V ----
#pragma unroll
            for (int ks = 0; ks < 4; ks++) {
                uint32_t ph[4], pl[4];
                {
                    float* e = s[2 * ks];
                    float* o = s[2 * ks + 1];
                    float eh0 = __bfloat162float(__float2bfloat16(e[0]));
                    float eh1 = __bfloat162float(__float2bfloat16(e[1]));
                    float eh2 = __bfloat162float(__float2bfloat16(e[2]));
                    float eh3 = __bfloat162float(__float2bfloat16(e[3]));
                    float oh0 = __bfloat162float(__float2bfloat16(o[0]));
                    float oh1 = __bfloat162float(__float2bfloat16(o[1]));
                    float oh2 = __bfloat162float(__float2bfloat16(o[2]));
                    float oh3 = __bfloat162float(__float2bfloat16(o[3]));
                    ph[0] = packbf2(eh0, eh1); ph[1] = packbf2(eh2, eh3);
                    ph[2] = packbf2(oh0, oh1); ph[3] = packbf2(oh2, oh3);
                    pl[0] = packbf2(e[0] - eh0, e[1] - eh1);
                    pl[1] = packbf2(e[2] - eh2, e[3] - eh3);
                    pl[2] = packbf2(o[0] - oh0, o[1] - oh1);
                    pl[3] = packbf2(o[2] - oh2, o[3] - oh3);
                }
                int keyr = ks * 16 + tkey;
#pragma unroll
                for (int np = 0; np < 4; np++) {
                    int nch = np * 2 + tnc;
                    uint32_t vh[4], vl[4];
                    ldsm4t(vh, sV  + keyr * 128 + ((nch ^ (keyr & 7)) * 16));
                    ldsm4t(vl, sVl + keyr * 128 + ((nch ^ (keyr & 7)) * 16));
                    uint32_t bh0[2] = {vh[0], vh[1]}, bh1[2] = {vh[2], vh[3]};
                    uint32_t bl0[2] = {vl[0], vl[1]}, bl1[2] = {vl[2], vl[3]};
                    mma16816(yacc[2 * np],     ph, bh0);
                    mma16816(yacc[2 * np],     ph, bl0);
                    mma16816(yacc[2 * np],     pl, bh0);
                    mma16816(yacc[2 * np + 1], ph, bh1);
                    mma16816(yacc[2 * np + 1], ph, bl1);
                    mma16816(yacc[2 * np + 1], pl, bh1);
                }
            }
        }
    }

    // ---- finalize: write fp32 y into g_qkv (viewed as y[4096][1024]) ----
    l0 += __shfl_xor_sync(0xffffffffu, l0, 1);
    l0 += __shfl_xor_sync(0xffffffffu, l0, 2);
    l1 += __shfl_xor_sync(0xffffffffu, l1, 1);
    l1 += __shfl_xor_sync(0xffffffffu, l1, 2);
    float inv0 = 1.f / l0, inv1 = 1.f / l1;

    int tok0 = b * S_ + qt * 128 + warp * 16 + (lane >> 2);
    int tok1 = tok0 + 8;
#pragma unroll
    for (int nf = 0; nf < 8; nf++) {
        int col = h * 64 + nf * 8 + (lane & 3) * 2;
        *(float2*)(g_qkv + (size_t)tok0 * E_ + col) =
            make_float2(yacc[nf][0] * inv0, yacc[nf][1] * inv0);
        *(float2*)(g_qkv + (size_t)tok1 * E_ + col) =
            make_float2(yacc[nf][2] * inv1, yacc[nf][3] * inv1);
    }
}

// ---------------------------------------------------------------------------
// launch — inputs: 0:x 1:ve 2:cos 3:sin 4:attn_mask 5:Wq 6:Wk 7:Wv 8:Wproj 9:Wgate
// ---------------------------------------------------------------------------
extern "C" void kernel_launch(void* const* d_in, const int* in_sizes, int n_in,
                              void* d_out, int out_size)
{
    (void)in_sizes; (void)n_in; (void)out_size;
    const float* x     = (const float*)d_in[0];
    const float* ve    = (const float*)d_in[1];
    const float* cosb  = (const float*)d_in[2];
    const float* sinb  = (const float*)d_in[3];
    const float* Wq    = (const float*)d_in[5];
    const float* Wk    = (const float*)d_in[6];
    const float* Wv    = (const float*)d_in[7];
    const float* Wproj = (const float*)d_in[8];
    const float* Wgate = (const float*)d_in[9];
    float* out = (float*)d_out;

    float* qkv;
    cudaGetSymbolAddress((void**)&qkv, g_qkv);
    int8_t *x1, *x2, *w1, *w2, *y1, *y2;
    float *xs, *ws, *ys;
    cudaGetSymbolAddress((void**)&x1, g_x1);
    cudaGetSymbolAddress((void**)&x2, g_x2);
    cudaGetSymbolAddress((void**)&xs, g_xs);
    cudaGetSymbolAddress((void**)&w1, g_w1);
    cudaGetSymbolAddress((void**)&w2, g_w2);
    cudaGetSymbolAddress((void**)&ws, g_ws);
    cudaGetSymbolAddress((void**)&y1, g_y1);
    cudaGetSymbolAddress((void**)&y2, g_y2);
    cudaGetSymbolAddress((void**)&ys, g_ys);

    static int smem_set = 0;
    if (!smem_set) {
        cudaFuncSetAttribute(attn_mma_kernel,
                             cudaFuncAttributeMaxDynamicSharedMemorySize, ATT_SMEM);
        cudaFuncSetAttribute(gemm_s8,
                             cudaFuncAttributeMaxDynamicSharedMemorySize, GS_SMEM);
        smem_set = 1;
    }

    // quantize activations + all weights (2 launches)
    quant_rows<<<TOKENS, 256>>>(x, x1, x2, xs);
    quantw_kernel<<<2560, 256>>>(Wq, Wk, Wv, Wproj);

    // fused QKV projection (int8 IMMA, K=32/instr)
    {
        dim3 g(1536 / 128, TOKENS / 128);
        gemm_s8<<<g, 256, GS_SMEM>>>(x1, x2, xs, w1, w2, ws, qkv, 1536, E_);
    }

    // gate + ve, rope + rmsnorm (emits bf16 hi/lo q,k,v)
    ew_kernel<<<TOKENS, 256>>>(x, ve, cosb, sinb, Wgate);

    // tensor-core flash attention (writes fp32 y into g_qkv[token][1024])
    {
        dim3 ga(S_ / 128, B_ * NH_);
        attn_mma_kernel<<<ga, 256, ATT_SMEM>>>();
    }

    // quantize y, then output projection (int8 IMMA)
    quant_rows<<<TOKENS, 256>>>(qkv, y1, y2, ys);
    {
        dim3 gp(E_ / 128, TOKENS / 128);
        gemm_s8<<<gp, 256, GS_SMEM>>>(y1, y2, ys, w1 + WP_OFF, w2 + WP_OFF,
                                      ws + 1536, out, E_, E_);
    }
}

// round 15
// speedup vs baseline: 2.1373x; 2.1373x over previous
#include <cuda_runtime.h>
#include <cuda_bf16.h>
#include <cuda_fp16.h>
#include <math.h>
#include <stdint.h>

#define B_   2
#define S_   2048
#define E_   1024
#define NH_  16
#define NKV_ 4
#define HD_  64
#define GATE_CH_ 12
#define TOKENS (B_ * S_)   // 4096

// ---------------------------------------------------------------------------
// Scratch (device globals: no allocation allowed)
// ---------------------------------------------------------------------------
__device__ float g_qkv[TOKENS * 1536];           // fused QKV output (q|k|v)

__device__ __nv_bfloat16 g_xh[TOKENS * E_];
__device__ __nv_bfloat16 g_xl[TOKENS * E_];
// attention operands: fp16 (2^-11 rounding)
__device__ __half g_qh[TOKENS * NH_ * HD_];
__device__ __half g_ql[TOKENS * NH_ * HD_];
__device__ __half g_kh[TOKENS * NKV_ * HD_];     // k single-term fp16
__device__ __half g_vh[TOKENS * NKV_ * HD_];
__device__ __half g_vl[TOKENS * NKV_ * HD_];
__device__ __nv_bfloat16 g_yh[TOKENS * E_];
__device__ __nv_bfloat16 g_yl[TOKENS * E_];
// weight rows: [Wq 0..1024 | Wk 1024..1280 | Wv 1280..1536 | Wproj 1536..2560]
#define WP_OFF (1536 * E_)
__device__ __nv_bfloat16 g_wh[2560 * E_];
__device__ __nv_bfloat16 g_wl[2560 * E_];

// ---------------------------------------------------------------------------
// PTX helpers
// ---------------------------------------------------------------------------
__device__ __forceinline__ void ldsm4(uint32_t* r, uint32_t addr)
{
    asm volatile("ldmatrix.sync.aligned.m8n8.x4.shared.b16 {%0,%1,%2,%3}, [%4];"
                 : "=r"(r[0]), "=r"(r[1]), "=r"(r[2]), "=r"(r[3]) : "r"(addr));
}
__device__ __forceinline__ void ldsm4t(uint32_t* r, uint32_t addr)
{
    asm volatile("ldmatrix.sync.aligned.m8n8.x4.trans.shared.b16 {%0,%1,%2,%3}, [%4];"
                 : "=r"(r[0]), "=r"(r[1]), "=r"(r[2]), "=r"(r[3]) : "r"(addr));
}
__device__ __forceinline__ void mma16816(float* c, const uint32_t* a, const uint32_t* b)
{
    asm volatile(
        "mma.sync.aligned.m16n8k16.row.col.f32.bf16.bf16.f32 "
        "{%0,%1,%2,%3},{%4,%5,%6,%7},{%8,%9},{%0,%1,%2,%3};"
        : "+f"(c[0]), "+f"(c[1]), "+f"(c[2]), "+f"(c[3])
        : "r"(a[0]), "r"(a[1]), "r"(a[2]), "r"(a[3]), "r"(b[0]), "r"(b[1]));
}
__device__ __forceinline__ void mma16816h(float* c, const uint32_t* a, const uint32_t* b)
{
    asm volatile(
        "mma.sync.aligned.m16n8k16.row.col.f32.f16.f16.f32 "
        "{%0,%1,%2,%3},{%4,%5,%6,%7},{%8,%9},{%0,%1,%2,%3};"
        : "+f"(c[0]), "+f"(c[1]), "+f"(c[2]), "+f"(c[3])
        : "r"(a[0]), "r"(a[1]), "r"(a[2]), "r"(a[3]), "r"(b[0]), "r"(b[1]));
}
__device__ __forceinline__ void cpasync16(uint32_t s, const void* g)
{
    asm volatile("cp.async.cg.shared.global [%0], [%1], 16;" :: "r"(s), "l"(g));
}
__device__ __forceinline__ void cpcommit() { asm volatile("cp.async.commit_group;"); }
template<int N> __device__ __forceinline__ void cpwait()
{ asm volatile("cp.async.wait_group %0;" :: "n"(N)); }

__device__ __forceinline__ uint32_t packbf2(float a, float b)
{
    __nv_bfloat162 t = __floats2bfloat162_rn(a, b);
    uint32_t u; memcpy(&u, &t, 4); return u;
}
__device__ __forceinline__ uint32_t packh2(float a, float b)
{
    __half2 t = __floats2half2_rn(a, b);
    uint32_t u; memcpy(&u, &t, 4); return u;
}

// ---------------------------------------------------------------------------
// split fp32 -> (hi, lo) bf16
// ---------------------------------------------------------------------------
__global__ __launch_bounds__(256)
void split_kernel(const float* __restrict__ in,
                  __nv_bfloat16* __restrict__ hi,
                  __nv_bfloat16* __restrict__ lo, int n4)
{
    int i = blockIdx.x * blockDim.x + threadIdx.x;
    if (i >= n4) return;
    float4 v = ((const float4*)in)[i];
    float vv[4] = {v.x, v.y, v.z, v.w};
    uint2 hv, lv;
    __nv_bfloat16* hp = (__nv_bfloat16*)&hv;
    __nv_bfloat16* lp = (__nv_bfloat16*)&lv;
#pragma unroll
    for (int j = 0; j < 4; j++) {
        __nv_bfloat16 h = __float2bfloat16(vv[j]);
        hp[j] = h;
        lp[j] = __float2bfloat16(vv[j] - __bfloat162float(h));
    }
    ((uint2*)hi)[i] = hv;
    ((uint2*)lo)[i] = lv;
}

// all four weight matrices -> one split buffer, one launch
__global__ __launch_bounds__(256)
void splitw_kernel(const float* __restrict__ Wq, const float* __restrict__ Wk,
                   const float* __restrict__ Wv, const float* __restrict__ Wp)
{
    int i = blockIdx.x * blockDim.x + threadIdx.x;  // quad id
    int e0 = i * 4;
    if (e0 >= 2560 * E_) return;
    int row = e0 >> 10, col = e0 & 1023;
    const float* src;
    if      (row < 1024) src = Wq + (size_t)row * E_ + col;
    else if (row < 1280) src = Wk + (size_t)(row - 1024) * E_ + col;
    else if (row < 1536) src = Wv + (size_t)(row - 1280) * E_ + col;
    else                 src = Wp + (size_t)(row - 1536) * E_ + col;
    float4 v = *(const float4*)src;
    float vv[4] = {v.x, v.y, v.z, v.w};
    uint2 hv, lv;
    __nv_bfloat16* hp = (__nv_bfloat16*)&hv;
    __nv_bfloat16* lp = (__nv_bfloat16*)&lv;
#pragma unroll
    for (int j = 0; j < 4; j++) {
        __nv_bfloat16 h = __float2bfloat16(vv[j]);
        hp[j] = h;
        lp[j] = __float2bfloat16(vv[j] - __bfloat162float(h));
    }
    ((uint2*)g_wh)[i] = hv;
    ((uint2*)g_wl)[i] = lv;
}

// ---------------------------------------------------------------------------
// Tensor-core GEMM (verified R9): 3-stage cp.async pipeline, 2 CTAs/SM.
// C = (Ah+Al)[M,K] @ (Wh+Wl)[N,K]^T   (3-term split bf16)
// ---------------------------------------------------------------------------
#define GSTG 32768
#define GEMM_SMEM (3 * GSTG)   // 96 KB

__global__ __launch_bounds__(256, 2)
void gemm_split_pipe(const __nv_bfloat16* __restrict__ Ah,
                     const __nv_bfloat16* __restrict__ Al,
                     const __nv_bfloat16* __restrict__ Wh,
                     const __nv_bfloat16* __restrict__ Wl,
                     float* __restrict__ C,
                     int M, int N, int K)
{
    extern __shared__ __align__(16) unsigned char gsm[];
    const uint32_t smBase = (uint32_t)__cvta_generic_to_shared(gsm);

    const int tid  = threadIdx.x;
    const int lane = tid & 31;
    const int warp = tid >> 5;
    const int wm = warp >> 2;
    const int wn = warp & 3;
    const int bm = blockIdx.y * 128;
    const int bn = blockIdx.x * 128;

    const int lchunk = tid & 7;
    const int lrow0  = tid >> 3;
    const __nv_bfloat16* Asrc = (lchunk < 4) ? Ah : Al;
    const __nv_bfloat16* Wsrc = (lchunk < 4) ? Wh : Wl;
    const int kcoloff = (lchunk & 3) * 8;

    const int niter = K >> 5;

    auto issue_stage = [&](int it) {
        uint32_t base = smBase + (it % 3) * GSTG;
        int k0 = it * 32;
#pragma unroll
        for (int r = 0; r < 4; r++) {
            int row = lrow0 + r * 32;
            uint32_t so = row * 128 + ((lchunk ^ (row & 7)) * 16);
            cpasync16(base + so,
                      Asrc + (size_t)(bm + row) * K + k0 + kcoloff);
            cpasync16(base + 16384 + so,
                      Wsrc + (size_t)(bn + row) * K + k0 + kcoloff);
        }
    };

    issue_stage(0); cpcommit();
    issue_stage(1); cpcommit();

    float acc[4][4][4];
#pragma unroll
    for (int i = 0; i < 4; i++)
#pragma unroll
        for (int j = 0; j < 4; j++)
#pragma unroll
            for (int r = 0; r < 4; r++) acc[i][j][r] = 0.f;

    const int a_r = lane & 15;
    const int a_c = (lane >> 4) & 1;
    const int b_r = ((lane >> 4) & 1) * 8 + (lane & 7);
    const int b_c = (lane >> 3) & 1;

    for (int i = 0; i < niter; i++) {
        cpwait<1>();
        __syncthreads();
        if (i + 2 < niter) issue_stage(i + 2);
        cpcommit();

        const uint32_t aB = smBase + (i % 3) * GSTG;
        const uint32_t wB = aB + 16384;

#pragma unroll
        for (int kk = 0; kk < 2; kk++) {
            uint32_t ah[4][4], wb[4][2];
#pragma unroll
            for (int mf = 0; mf < 4; mf++) {
                int R = wm * 64 + mf * 16 + a_r;
                int chi = kk * 2 + a_c;
                ldsm4(ah[mf], aB + R * 128 + ((chi ^ (R & 7)) * 16));
            }
#pragma unroll
            for (int np = 0; np < 2; np++) {
                int R = wn * 32 + np * 16 + b_r;
                int chi = kk * 2 + b_c;
                uint32_t t[4];
                ldsm4(t, wB + R * 128 + ((chi ^ (R & 7)) * 16));
                wb[2 * np][0] = t[0]; wb[2 * np][1] = t[1];
                wb[2 * np + 1][0] = t[2]; wb[2 * np + 1][1] = t[3];
            }
#pragma unroll
            for (int mf = 0; mf < 4; mf++)
#pragma unroll
                for (int nf = 0; nf < 4; nf++)
                    mma16816(acc[mf][nf], ah[mf], wb[nf]);

            uint32_t wl[4][2];
#pragma unroll
            for (int np = 0; np < 2; np++) {
                int R = wn * 32 + np * 16 + b_r;
                int chi = kk * 2 + b_c;
                uint32_t t[4];
                ldsm4(t, wB + R * 128 + (((chi + 4) ^ (R & 7)) * 16));
                wl[2 * np][0] = t[0]; wl[2 * np][1] = t[1];
                wl[2 * np + 1][0] = t[2]; wl[2 * np + 1][1] = t[3];
            }
#pragma unroll
            for (int mf = 0; mf < 4; mf++)
#pragma unroll
                for (int nf = 0; nf < 4; nf++)
                    mma16816(acc[mf][nf], ah[mf], wl[nf]);

#pragma unroll
            for (int mf = 0; mf < 4; mf++) {
                int R = wm * 64 + mf * 16 + a_r;
                int chi = kk * 2 + a_c;
                ldsm4(ah[mf], aB + R * 128 + (((chi + 4) ^ (R & 7)) * 16));
            }
#pragma unroll
            for (int mf = 0; mf < 4; mf++)
#pragma unroll
                for (int nf = 0; nf < 4; nf++)
                    mma16816(acc[mf][nf], ah[mf], wb[nf]);
        }
    }

#pragma unroll
    for (int mf = 0; mf < 4; mf++)
#pragma unroll
        for (int nf = 0; nf < 4; nf++) {
            int row0 = bm + wm * 64 + mf * 16 + (lane >> 2);
            int col  = bn + wn * 32 + nf * 8 + (lane & 3) * 2;
            float* c = acc[mf][nf];
            *(float2*)(C + (size_t)row0 * N + col)       = make_float2(c[0], c[1]);
            *(float2*)(C + (size_t)(row0 + 8) * N + col) = make_float2(c[2], c[3]);
        }
}

// ---------------------------------------------------------------------------
// Elementwise: gate+ve on V, rope+rmsnorm(*1.2) on Q,K; reads fused g_qkv,
// emits fp16: q hi/lo, k single, v hi/lo.
// ---------------------------------------------------------------------------
__global__ __launch_bounds__(256)
void ew_kernel(const float* __restrict__ x,
               const float* __restrict__ ve,
               const float* __restrict__ cosb,
               const float* __restrict__ sinb,
               const float* __restrict__ Wgate)
{
    const int token = blockIdx.x;
    const int s = token % S_;
    const int tid = threadIdx.x;

    __shared__ float gate_s[NKV_];
    __shared__ float cs[32], sn[32];

    if (tid < 32) {
        cs[tid] = cosb[s * 32 + tid];
        sn[tid] = sinb[s * 32 + tid];
    }
    if (tid >= 32 && tid < 32 + NKV_) {
        int kv = tid - 32;
        float acc = 0.f;
#pragma unroll
        for (int c = 0; c < GATE_CH_; c++)
            acc += x[(size_t)token * E_ + c] * Wgate[kv * GATE_CH_ + c];
        gate_s[kv] = 3.f / (1.f + expf(-acc));
    }
    __syncthreads();

    {   // v = v + gate*ve, fp16 split
        int kv = tid >> 6;
        float g = gate_s[kv];
        float v = g_qkv[(size_t)token * 1536 + 1280 + tid] + g * ve[(size_t)token * 256 + tid];
        size_t idx = (size_t)token * (NKV_ * HD_) + tid;
        __half h = __float2half(v);
        g_vh[idx] = h;
        g_vl[idx] = __float2half(v - __half2float(h));
    }

    const int warp = tid >> 5, lane = tid & 31;
    const float c = cs[lane], si = sn[lane];

    for (int hh = warp; hh < NH_ + NKV_; hh += 8) {
        const float* base;
        if (hh < NH_) base = g_qkv + (size_t)token * 1536 + hh * HD_;
        else          base = g_qkv + (size_t)token * 1536 + 1024 + (hh - NH_) * HD_;

        float x1 = base[lane];
        float x2 = base[lane + 32];
        float o1 =  x1 * c  + x2 * si;
        float o2 = -x1 * si + x2 * c;

        float ss = o1 * o1 + o2 * o2;
#pragma unroll
        for (int o = 16; o > 0; o >>= 1)
            ss += __shfl_xor_sync(0xffffffffu, ss, o);
        float r = rsqrtf(ss * (1.f / HD_) + 1.1920929e-7f) * 1.2f;
        float r1 = o1 * r, r2 = o2 * r;

        if (hh < NH_) {          // q: fp16 hi/lo
            size_t off = (size_t)token * (NH_ * HD_) + hh * HD_;
            __half h1 = __float2half(r1);
            __half h2 = __float2half(r2);
            g_qh[off + lane]      = h1;
            g_qh[off + lane + 32] = h2;
            g_ql[off + lane]      = __float2half(r1 - __half2float(h1));
            g_ql[off + lane + 32] = __float2half(r2 - __half2float(h2));
        } else {                 // k: single fp16
            size_t off = (size_t)token * (NKV_ * HD_) + (hh - NH_) * HD_;
            g_kh[off + lane]      = __float2half(r1);
            g_kh[off + lane + 32] = __float2half(r2);
        }
    }
}

// ---------------------------------------------------------------------------
// Tensor-core flash attention (fp16 asymmetric). 128 q-rows/block, 8 warps,
// 64-key tiles, 3-stage K/V ring.
// QK: (qh+ql)·k — 2 mma/step; PV: p·(vh+vl) — 2 mma/step.
// Stage = kh 8K | vh 8K | vl 8K = 24KB; Q hi/lo 32K; total 104KB.
// ---------------------------------------------------------------------------
#define ASMQ_L 16384
#define ASMKV  32768
#define ASTG   24576
#define ATT_SMEM (ASMKV + 3 * ASTG)   // 106496

__global__ void __launch_bounds__(256, 1) attn_mma_kernel()
{
    extern __shared__ __align__(16) unsigned char sm[];
    const int qt = (int)gridDim.x - 1 - (int)blockIdx.x;  // longest-first
    const int bh = blockIdx.y;
    const int b = bh / NH_, h = bh % NH_;
    const int kvh = h >> 2;

    const int tid = threadIdx.x;
    const int lane = tid & 31;
    const int warp = tid >> 5;          // 0..7

    const uint32_t smBase = (uint32_t)__cvta_generic_to_shared(sm);

    const int chunk = tid & 7;
    const int row0  = tid >> 3;         // 0..31

    // ---- load Q (hi/lo fp16), 128 rows, swizzled (row = 128B = 64 fp16) ----
#pragma unroll
    for (int it = 0; it < 4; it++) {
        int row = row0 + it * 32;
        size_t g = ((size_t)(b * S_ + qt * 128 + row) * NH_ + h) * HD_ + chunk * 8;
        uint32_t so = row * 128 + ((chunk ^ (row & 7)) * 16);
        *(uint4*)(sm + so)          = *(const uint4*)(g_qh + g);
        *(uint4*)(sm + ASMQ_L + so) = *(const uint4*)(g_ql + g);
    }

    auto issue_kv = [&](int t) {
        uint32_t stg = smBase + ASMKV + (t % 3) * ASTG;
#pragma unroll
        for (int it = 0; it < 2; it++) {
            int row = row0 + it * 32;
            size_t g = ((size_t)(b * S_ + t * 64 + row) * NKV_ + kvh) * HD_ + chunk * 8;
            uint32_t so = row * 128 + ((chunk ^ (row & 7)) * 16);
            cpasync16(stg + so,         g_kh + g);
            cpasync16(stg + 8192 + so,  g_vh + g);
            cpasync16(stg + 16384 + so, g_vl + g);
        }
        cpcommit();
    };

    const int tmax = 2 * qt + 1;
    issue_kv(0);
    if (tmax >= 1) issue_kv(1);

    __syncthreads();   // Q ready

    // ---- Q fragments (hi + lo) ----
    const int a_r = lane & 15;
    const int a_c = (lane >> 4) & 1;
    uint32_t qfh[4][4], qfl[4][4];
    {
        int R = warp * 16 + a_r;
#pragma unroll
        for (int ks = 0; ks < 4; ks++) {
            int chi = ks * 2 + a_c;
            ldsm4(qfh[ks], smBase + R * 128 + ((chi ^ (R & 7)) * 16));
            ldsm4(qfl[ks], smBase + ASMQ_L + R * 128 + ((chi ^ (R & 7)) * 16));
        }
    }

    const int b_r = ((lane >> 4) & 1) * 8 + (lane & 7);
    const int b_c = (lane >> 3) & 1;
    const int t_grp = lane >> 3, t_off = lane & 7;
    const int tkey = ((t_grp & 1) * 8) + t_off;
    const int tnc  = t_grp >> 1;

    float yacc[8][4];
#pragma unroll
    for (int nf = 0; nf < 8; nf++)
#pragma unroll
        for (int r = 0; r < 4; r++) yacc[nf][r] = 0.f;
    float m0 = -INFINITY, m1 = -INFINITY, l0 = 0.f, l1 = 0.f;

    const float c2 = 0.125f * 1.44269504f;   // scale * log2(e)
    const int r0q = qt * 128 + warp * 16 + (lane >> 2);
    const int warp_last = qt * 128 + warp * 16 + 15;

    for (int t = 0; t <= tmax; t++) {
        if (t + 1 <= tmax) cpwait<1>();
        else               cpwait<0>();
        __syncthreads();   // everyone done reading stage (t-1)%3; stage t ready
        if (t + 2 <= tmax) issue_kv(t + 2);   // safe: fills (t-1)%3 post-barrier

        const bool skip = warp_last < t * 64;
        if (!skip) {
            const uint32_t sK  = smBase + ASMKV + (t % 3) * ASTG;
            const uint32_t sV  = sK + 8192;
            const uint32_t sVl = sK + 16384;

            // ---- S = Q K^T  (k single-term fp16) ----
            float s[8][4];
#pragma unroll
            for (int nf = 0; nf < 8; nf++)
#pragma unroll
                for (int r = 0; r < 4; r++) s[nf][r] = 0.f;

#pragma unroll
            for (int ks = 0; ks < 4; ks++) {
                uint32_t kb[8][2];
#pragma unroll
                for (int np = 0; np < 4; np++) {
                    int R = np * 16 + b_r;
                    int chi = ks * 2 + b_c;
                    uint32_t tt[4];
                    ldsm4(tt, sK + R * 128 + ((chi ^ (R & 7)) * 16));
                    kb[2 * np][0] = tt[0]; kb[2 * np][1] = tt[1];
                    kb[2 * np + 1][0] = tt[2]; kb[2 * np + 1][1] = tt[3];
                }
#pragma unroll
                for (int nf = 0; nf < 8; nf++) {
                    mma16816h(s[nf], qfh[ks], kb[nf]);
                    mma16816h(s[nf], qfl[ks], kb[nf]);
                }
            }

            // ---- causal mask (only possible on last two tiles) ----
            if (t >= 2 * qt) {
#pragma unroll
                for (int nf = 0; nf < 8; nf++) {
                    int c0 = t * 64 + nf * 8 + (lane & 3) * 2;
                    if (c0 > r0q)          s[nf][0] = -INFINITY;
                    if (c0 + 1 > r0q)      s[nf][1] = -INFINITY;
                    if (c0 > r0q + 8)      s[nf][2] = -INFINITY;
                    if (c0 + 1 > r0q + 8)  s[nf][3] = -INFINITY;
                }
            }

            // ---- online softmax (base-2) ----
            float tm0 = -INFINITY, tm1 = -INFINITY;
#pragma unroll
            for (int nf = 0; nf < 8; nf++) {
                tm0 = fmaxf(tm0, fmaxf(s[nf][0], s[nf][1]));
                tm1 = fmaxf(tm1, fmaxf(s[nf][2], s[nf][3]));
            }
            tm0 = fmaxf(tm0, __shfl_xor_sync(0xffffffffu, tm0, 1));
            tm0 = fmaxf(tm0, __shfl_xor_sync(0xffffffffu, tm0, 2));
            tm1 = fmaxf(tm1, __shfl_xor_sync(0xffffffffu, tm1, 1));
            tm1 = fmaxf(tm1, __shfl_xor_sync(0xffffffffu, tm1, 2));

            float mn0 = fmaxf(m0, tm0), mn1 = fmaxf(m1, tm1);
            float mb0 = mn0 * c2, mb1 = mn1 * c2;
            float cr0 = exp2f(m0 * c2 - mb0);
            float cr1 = exp2f(m1 * c2 - mb1);
            l0 *= cr0; l1 *= cr1;
#pragma unroll
            for (int nf = 0; nf < 8; nf++) {
                yacc[nf][0] *= cr0; yacc[nf][1] *= cr0;
                yacc[nf][2] *= cr1; yacc[nf][3] *= cr1;
            }
#pragma unroll
            for (int nf = 0; nf < 8; nf++) {
                s[nf][0] = exp2f(fmaf(s[nf][0], c2, -mb0));
                s[nf][1] = exp2f(fmaf(s[nf][1], c2, -mb0));
                s[nf][2] = exp2f(fmaf(s[nf][2], c2, -mb1));
                s[nf][3] = exp2f(fmaf(s[nf][3], c2, -mb1));
                l0 += s[nf][0] + s[nf][1];
                l1 += s[nf][2] + s[nf][3];
            }
            m0 = mn0; m1 = mn1;

            // ---- y += P V  (P single fp16, V 2-term fp16) ----
#pragma unroll
            for (int ks = 0; ks < 4; ks++) {
                uint32_t ph[4];
                {
                    float* e = s[2 * ks];
                    float* o = s[2 * ks + 1];
                    ph[0] = packh2(e[0], e[1]); ph[1] = packh2(e[2], e[3]);
                    ph[2] = packh2(o[0], o[1]); ph[3] = packh2(o[2], o[3]);
                }
                int keyr = ks * 16 + tkey;
#pragma unroll
                for (int np = 0; np < 4; np++) {
                    int nch = np * 2 + tnc;
                    uint32_t vh[4], vl[4];
                    ldsm4t(vh, sV  + keyr * 128 + ((nch ^ (keyr & 7)) * 16));
                    ldsm4t(vl, sVl + keyr * 128 + ((nch ^ (keyr & 7)) * 16));
                    uint32_t bh0[2] = {vh[0], vh[1]}, bh1[2] = {vh[2], vh[3]};
                    uint32_t bl0[2] = {vl[0], vl[1]}, bl1[2] = {vl[2], vl[3]};
                    mma16816h(yacc[2 * np],     ph, bh0);
                    mma16816h(yacc[2 * np],     ph, bl0);
                    mma16816h(yacc[2 * np + 1], ph, bh1);
                    mma16816h(yacc[2 * np + 1], ph, bl1);
                }
            }
        }
    }

    // ---- finalize: normalize, store bf16 hi/lo y ----
    l0 += __shfl_xor_sync(0xffffffffu, l0, 1);
    l0 += __shfl_xor_sync(0xffffffffu, l0, 2);
    l1 += __shfl_xor_sync(0xffffffffu, l1, 1);
    l1 += __shfl_xor_sync(0xffffffffu, l1, 2);
    float inv0 = 1.f / l0, inv1 = 1.f / l1;

    int tok0 = b * S_ + qt * 128 + warp * 16 + (lane >> 2);
    int tok1 = tok0 + 8;
#pragma unroll
    for (int nf = 0; nf < 8; nf++) {
        int col = h * 64 + nf * 8 + (lane & 3) * 2;
        float y0 = yacc[nf][0] * inv0, y1 = yacc[nf][1] * inv0;
        float y2 = yacc[nf][2] * inv1, y3 = yacc[nf][3] * inv1;
        float h0 = __bfloat162float(__float2bfloat16(y0));
        float h1 = __bfloat162float(__float2bfloat16(y1));
        float h2 = __bfloat162float(__float2bfloat16(y2));
        float h3 = __bfloat162float(__float2bfloat16(y3));
        *(uint32_t*)(g_yh + (size_t)tok0 * E_ + col) = packbf2(h0, h1);
        *(uint32_t*)(g_yl + (size_t)tok0 * E_ + col) = packbf2(y0 - h0, y1 - h1);
        *(uint32_t*)(g_yh + (size_t)tok1 * E_ + col) = packbf2(h2, h3);
        *(uint32_t*)(g_yl + (size_t)tok1 * E_ + col) = packbf2(y2 - h2, y3 - h3);
    }
}

// ---------------------------------------------------------------------------
// launch — inputs: 0:x 1:ve 2:cos 3:sin 4:attn_mask 5:Wq 6:Wk 7:Wv 8:Wproj 9:Wgate
// ---------------------------------------------------------------------------
extern "C" void kernel_launch(void* const* d_in, const int* in_sizes, int n_in,
                              void* d_out, int out_size)
{
    (void)in_sizes; (void)n_in; (void)out_size;
    const float* x     = (const float*)d_in[0];
    const float* ve    = (const float*)d_in[1];
    const float* cosb  = (const float*)d_in[2];
    const float* sinb  = (const float*)d_in[3];
    const float* Wq    = (const float*)d_in[5];
    const float* Wk    = (const float*)d_in[6];
    const float* Wv    = (const float*)d_in[7];
    const float* Wproj = (const float*)d_in[8];
    const float* Wgate = (const float*)d_in[9];
    float* out = (float*)d_out;

    float* qkv;
    cudaGetSymbolAddress((void**)&qkv, g_qkv);
    __nv_bfloat16 *xh, *xl, *yh, *yl, *wh, *wl;
    cudaGetSymbolAddress((void**)&xh, g_xh);
    cudaGetSymbolAddress((void**)&xl, g_xl);
    cudaGetSymbolAddress((void**)&yh, g_yh);
    cudaGetSymbolAddress((void**)&yl, g_yl);
    cudaGetSymbolAddress((void**)&wh, g_wh);
    cudaGetSymbolAddress((void**)&wl, g_wl);

    static int smem_set = 0;
    if (!smem_set) {
        cudaFuncSetAttribute(attn_mma_kernel,
                             cudaFuncAttributeMaxDynamicSharedMemorySize, ATT_SMEM);
        cudaFuncSetAttribute(gemm_split_pipe,
                             cudaFuncAttributeMaxDynamicSharedMemorySize, GEMM_SMEM);
        smem_set = 1;
    }

    // splits (2 launches)
    {
        int n4 = TOKENS * E_ / 4;
        split_kernel<<<(n4 + 255) / 256, 256>>>(x, xh, xl, n4);
        int w4 = 2560 * E_ / 4;
        splitw_kernel<<<(w4 + 255) / 256, 256>>>(Wq, Wk, Wv, Wproj);
    }

    // fused QKV projection (bf16 3-term, verified)
    {
        dim3 g(1536 / 128, TOKENS / 128);
        gemm_split_pipe<<<g, 256, GEMM_SMEM>>>(xh, xl, wh, wl, qkv,
                                               TOKENS, 1536, E_);
    }

    // gate + ve, rope + rmsnorm (emits fp16 q hi/lo, k single, v hi/lo)
    ew_kernel<<<TOKENS, 256>>>(x, ve, cosb, sinb, Wgate);

    // fp16 tensor-core flash attention (emits bf16 hi/lo y)
    {
        dim3 ga(S_ / 128, B_ * NH_);
        attn_mma_kernel<<<ga, 256, ATT_SMEM>>>();
    }

    // output projection (bf16 3-term, verified)
    {
        dim3 gp(E_ / 128, TOKENS / 128);
        gemm_split_pipe<<<gp, 256, GEMM_SMEM>>>(yh, yl, wh + WP_OFF, wl + WP_OFF,
                                                out, TOKENS, E_, E_);
    }
}

// round 16
// speedup vs baseline: 2.7622x; 1.2924x over previous
#include <cuda_runtime.h>
#include <cuda_bf16.h>
#include <cuda_fp16.h>
#include <math.h>
#include <stdint.h>

#define B_   2
#define S_   2048
#define E_   1024
#define NH_  16
#define NKV_ 4
#define HD_  64
#define GATE_CH_ 12
#define TOKENS (B_ * S_)   // 4096

// ---------------------------------------------------------------------------
// Scratch (device globals: no allocation allowed)
// ---------------------------------------------------------------------------
__device__ float g_qkv[TOKENS * 1536];           // fused QKV output (q|k|v)

// fp16 operands everywhere (2^-11 rounding)
__device__ __half g_xh[TOKENS * E_];
__device__ __half g_xl[TOKENS * E_];
__device__ __half g_qh[TOKENS * NH_ * HD_];      // q single fp16
__device__ __half g_kh[TOKENS * NKV_ * HD_];     // k single fp16
__device__ __half g_vh[TOKENS * NKV_ * HD_];
__device__ __half g_vl[TOKENS * NKV_ * HD_];
__device__ __half g_yh[TOKENS * E_];
__device__ __half g_yl[TOKENS * E_];
// weight rows: [Wq 0..1024 | Wk 1024..1280 | Wv 1280..1536 | Wproj 1536..2560]
#define WP_OFF (1536 * E_)
__device__ __half g_w[2560 * E_];                // W single fp16

// ---------------------------------------------------------------------------
// PTX helpers
// ---------------------------------------------------------------------------
__device__ __forceinline__ void ldsm4(uint32_t* r, uint32_t addr)
{
    asm volatile("ldmatrix.sync.aligned.m8n8.x4.shared.b16 {%0,%1,%2,%3}, [%4];"
                 : "=r"(r[0]), "=r"(r[1]), "=r"(r[2]), "=r"(r[3]) : "r"(addr));
}
__device__ __forceinline__ void ldsm4t(uint32_t* r, uint32_t addr)
{
    asm volatile("ldmatrix.sync.aligned.m8n8.x4.trans.shared.b16 {%0,%1,%2,%3}, [%4];"
                 : "=r"(r[0]), "=r"(r[1]), "=r"(r[2]), "=r"(r[3]) : "r"(addr));
}
__device__ __forceinline__ void mma16816h(float* c, const uint32_t* a, const uint32_t* b)
{
    asm volatile(
        "mma.sync.aligned.m16n8k16.row.col.f32.f16.f16.f32 "
        "{%0,%1,%2,%3},{%4,%5,%6,%7},{%8,%9},{%0,%1,%2,%3};"
        : "+f"(c[0]), "+f"(c[1]), "+f"(c[2]), "+f"(c[3])
        : "r"(a[0]), "r"(a[1]), "r"(a[2]), "r"(a[3]), "r"(b[0]), "r"(b[1]));
}
__device__ __forceinline__ void cpasync16(uint32_t s, const void* g)
{
    asm volatile("cp.async.cg.shared.global [%0], [%1], 16;" :: "r"(s), "l"(g));
}
__device__ __forceinline__ void cpcommit() { asm volatile("cp.async.commit_group;"); }
template<int N> __device__ __forceinline__ void cpwait()
{ asm volatile("cp.async.wait_group %0;" :: "n"(N)); }

__device__ __forceinline__ uint32_t packh2(float a, float b)
{
    __half2 t = __floats2half2_rn(a, b);
    uint32_t u; memcpy(&u, &t, 4); return u;
}

// ---------------------------------------------------------------------------
// split fp32 -> (hi, lo) fp16
// ---------------------------------------------------------------------------
__global__ __launch_bounds__(256)
void split_kernel(const float* __restrict__ in,
                  __half* __restrict__ hi, __half* __restrict__ lo, int n4)
{
    int i = blockIdx.x * blockDim.x + threadIdx.x;
    if (i >= n4) return;
    float4 v = ((const float4*)in)[i];
    float vv[4] = {v.x, v.y, v.z, v.w};
    uint2 hv, lv;
    __half* hp = (__half*)&hv;
    __half* lp = (__half*)&lv;
#pragma unroll
    for (int j = 0; j < 4; j++) {
        __half h = __float2half(vv[j]);
        hp[j] = h;
        lp[j] = __float2half(vv[j] - __half2float(h));
    }
    ((uint2*)hi)[i] = hv;
    ((uint2*)lo)[i] = lv;
}

// all four weight matrices -> one fp16 buffer, one launch
__global__ __launch_bounds__(256)
void splitw_kernel(const float* __restrict__ Wq, const float* __restrict__ Wk,
                   const float* __restrict__ Wv, const float* __restrict__ Wp)
{
    int i = blockIdx.x * blockDim.x + threadIdx.x;  // quad id
    int e0 = i * 4;
    if (e0 >= 2560 * E_) return;
    int row = e0 >> 10, col = e0 & 1023;
    const float* src;
    if      (row < 1024) src = Wq + (size_t)row * E_ + col;
    else if (row < 1280) src = Wk + (size_t)(row - 1024) * E_ + col;
    else if (row < 1536) src = Wv + (size_t)(row - 1280) * E_ + col;
    else                 src = Wp + (size_t)(row - 1536) * E_ + col;
    float4 v = *(const float4*)src;
    uint2 hv;
    __half* hp = (__half*)&hv;
    hp[0] = __float2half(v.x); hp[1] = __float2half(v.y);
    hp[2] = __float2half(v.z); hp[3] = __float2half(v.w);
    ((uint2*)g_w)[i] = hv;
}

// ---------------------------------------------------------------------------
// fp16 2-term GEMM: C = (Ah+Al)[M,K] @ W[N,K]^T, 3-stage cp.async, 2 CTAs/SM.
// tile 128x128, BK=32. A row 128B = [Ah k0..31 | Al k0..31]; W row 128B with
// only chunks 0-3 (Wh k0..31) written/read — upper half unused.
// Per kk: (ah,wb)->16mma, (al reuse regs)->16mma.
// ---------------------------------------------------------------------------
#define GSTG 32768
#define GEMM_SMEM (3 * GSTG)   // 96 KB

__global__ __launch_bounds__(256, 2)
void gemm_h2(const __half* __restrict__ Ah, const __half* __restrict__ Al,
             const __half* __restrict__ W,
             float* __restrict__ C, int M, int N, int K)
{
    extern __shared__ __align__(16) unsigned char gsm[];
    const uint32_t smBase = (uint32_t)__cvta_generic_to_shared(gsm);

    const int tid  = threadIdx.x;
    const int lane = tid & 31;
    const int warp = tid >> 5;
    const int wm = warp >> 2;
    const int wn = warp & 3;
    const int bm = blockIdx.y * 128;
    const int bn = blockIdx.x * 128;

    const int lchunk = tid & 7;
    const int lrow0  = tid >> 3;
    const __half* Asrc = (lchunk < 4) ? Ah : Al;
    const int kcoloff = (lchunk & 3) * 8;

    const int niter = K >> 5;

    auto issue_stage = [&](int it) {
        uint32_t base = smBase + (it % 3) * GSTG;
        int k0 = it * 32;
#pragma unroll
        for (int r = 0; r < 4; r++) {
            int row = lrow0 + r * 32;
            uint32_t so = row * 128 + ((lchunk ^ (row & 7)) * 16);
            cpasync16(base + so,
                      Asrc + (size_t)(bm + row) * K + k0 + kcoloff);
            if (lchunk < 4)
                cpasync16(base + 16384 + so,
                          W + (size_t)(bn + row) * K + k0 + kcoloff);
        }
    };

    issue_stage(0); cpcommit();
    issue_stage(1); cpcommit();

    float acc[4][4][4];
#pragma unroll
    for (int i = 0; i < 4; i++)
#pragma unroll
        for (int j = 0; j < 4; j++)
#pragma unroll
            for (int r = 0; r < 4; r++) acc[i][j][r] = 0.f;

    const int a_r = lane & 15;
    const int a_c = (lane >> 4) & 1;
    const int b_r = ((lane >> 4) & 1) * 8 + (lane & 7);
    const int b_c = (lane >> 3) & 1;

    for (int i = 0; i < niter; i++) {
        cpwait<1>();
        __syncthreads();
        if (i + 2 < niter) issue_stage(i + 2);
        cpcommit();

        const uint32_t aB = smBase + (i % 3) * GSTG;
        const uint32_t wB = aB + 16384;

#pragma unroll
        for (int kk = 0; kk < 2; kk++) {
            uint32_t ah[4][4], wb[4][2];
#pragma unroll
            for (int mf = 0; mf < 4; mf++) {
                int R = wm * 64 + mf * 16 + a_r;
                int chi = kk * 2 + a_c;
                ldsm4(ah[mf], aB + R * 128 + ((chi ^ (R & 7)) * 16));
            }
#pragma unroll
            for (int np = 0; np < 2; np++) {
                int R = wn * 32 + np * 16 + b_r;
                int chi = kk * 2 + b_c;
                uint32_t t[4];
                ldsm4(t, wB + R * 128 + ((chi ^ (R & 7)) * 16));
                wb[2 * np][0] = t[0]; wb[2 * np][1] = t[1];
                wb[2 * np + 1][0] = t[2]; wb[2 * np + 1][1] = t[3];
            }
#pragma unroll
            for (int mf = 0; mf < 4; mf++)
#pragma unroll
                for (int nf = 0; nf < 4; nf++)
                    mma16816h(acc[mf][nf], ah[mf], wb[nf]);

            // lo pass: reuse ah registers
#pragma unroll
            for (int mf = 0; mf < 4; mf++) {
                int R = wm * 64 + mf * 16 + a_r;
                int chi = kk * 2 + a_c;
                ldsm4(ah[mf], aB + R * 128 + (((chi + 4) ^ (R & 7)) * 16));
            }
#pragma unroll
            for (int mf = 0; mf < 4; mf++)
#pragma unroll
                for (int nf = 0; nf < 4; nf++)
                    mma16816h(acc[mf][nf], ah[mf], wb[nf]);
        }
    }

#pragma unroll
    for (int mf = 0; mf < 4; mf++)
#pragma unroll
        for (int nf = 0; nf < 4; nf++) {
            int row0 = bm + wm * 64 + mf * 16 + (lane >> 2);
            int col  = bn + wn * 32 + nf * 8 + (lane & 3) * 2;
            float* c = acc[mf][nf];
            *(float2*)(C + (size_t)row0 * N + col)       = make_float2(c[0], c[1]);
            *(float2*)(C + (size_t)(row0 + 8) * N + col) = make_float2(c[2], c[3]);
        }
}

// ---------------------------------------------------------------------------
// Elementwise: gate+ve on V, rope+rmsnorm(*1.2) on Q,K; reads fused g_qkv,
// emits fp16: q single, k single, v hi/lo.
// ---------------------------------------------------------------------------
__global__ __launch_bounds__(256)
void ew_kernel(const float* __restrict__ x,
               const float* __restrict__ ve,
               const float* __restrict__ cosb,
               const float* __restrict__ sinb,
               const float* __restrict__ Wgate)
{
    const int token = blockIdx.x;
    const int s = token % S_;
    const int tid = threadIdx.x;

    __shared__ float gate_s[NKV_];
    __shared__ float cs[32], sn[32];

    if (tid < 32) {
        cs[tid] = cosb[s * 32 + tid];
        sn[tid] = sinb[s * 32 + tid];
    }
    if (tid >= 32 && tid < 32 + NKV_) {
        int kv = tid - 32;
        float acc = 0.f;
#pragma unroll
        for (int c = 0; c < GATE_CH_; c++)
            acc += x[(size_t)token * E_ + c] * Wgate[kv * GATE_CH_ + c];
        gate_s[kv] = 3.f / (1.f + expf(-acc));
    }
    __syncthreads();

    {   // v = v + gate*ve, fp16 split
        int kv = tid >> 6;
        float g = gate_s[kv];
        float v = g_qkv[(size_t)token * 1536 + 1280 + tid] + g * ve[(size_t)token * 256 + tid];
        size_t idx = (size_t)token * (NKV_ * HD_) + tid;
        __half h = __float2half(v);
        g_vh[idx] = h;
        g_vl[idx] = __float2half(v - __half2float(h));
    }

    const int warp = tid >> 5, lane = tid & 31;
    const float c = cs[lane], si = sn[lane];

    for (int hh = warp; hh < NH_ + NKV_; hh += 8) {
        const float* base;
        if (hh < NH_) base = g_qkv + (size_t)token * 1536 + hh * HD_;
        else          base = g_qkv + (size_t)token * 1536 + 1024 + (hh - NH_) * HD_;

        float x1 = base[lane];
        float x2 = base[lane + 32];
        float o1 =  x1 * c  + x2 * si;
        float o2 = -x1 * si + x2 * c;

        float ss = o1 * o1 + o2 * o2;
#pragma unroll
        for (int o = 16; o > 0; o >>= 1)
            ss += __shfl_xor_sync(0xffffffffu, ss, o);
        float r = rsqrtf(ss * (1.f / HD_) + 1.1920929e-7f) * 1.2f;
        float r1 = o1 * r, r2 = o2 * r;

        if (hh < NH_) {          // q: single fp16
            size_t off = (size_t)token * (NH_ * HD_) + hh * HD_;
            g_qh[off + lane]      = __float2half(r1);
            g_qh[off + lane + 32] = __float2half(r2);
        } else {                 // k: single fp16
            size_t off = (size_t)token * (NKV_ * HD_) + (hh - NH_) * HD_;
            g_kh[off + lane]      = __float2half(r1);
            g_kh[off + lane + 32] = __float2half(r2);
        }
    }
}

// ---------------------------------------------------------------------------
// fp16 flash attention. 128 q-rows/block, 8 warps, 64-key tiles, 3-stage ring.
// QK: q·k — 1 mma/step; PV: p·(vh+vl) — 2 mma/step.
// Q 16K; stage = kh 8K | vh 8K | vl 8K = 24KB; total 88KB.
// ---------------------------------------------------------------------------
#define ASMKV  16384
#define ASTG   24576
#define ATT_SMEM (ASMKV + 3 * ASTG)   // 90112

__global__ void __launch_bounds__(256, 1) attn_mma_kernel()
{
    extern __shared__ __align__(16) unsigned char sm[];
    const int qt = (int)gridDim.x - 1 - (int)blockIdx.x;  // longest-first
    const int bh = blockIdx.y;
    const int b = bh / NH_, h = bh % NH_;
    const int kvh = h >> 2;

    const int tid = threadIdx.x;
    const int lane = tid & 31;
    const int warp = tid >> 5;          // 0..7

    const uint32_t smBase = (uint32_t)__cvta_generic_to_shared(sm);

    const int chunk = tid & 7;
    const int row0  = tid >> 3;         // 0..31

    // ---- load Q (single fp16), 128 rows, swizzled ----
#pragma unroll
    for (int it = 0; it < 4; it++) {
        int row = row0 + it * 32;
        size_t g = ((size_t)(b * S_ + qt * 128 + row) * NH_ + h) * HD_ + chunk * 8;
        uint32_t so = row * 128 + ((chunk ^ (row & 7)) * 16);
        *(uint4*)(sm + so) = *(const uint4*)(g_qh + g);
    }

    auto issue_kv = [&](int t) {
        uint32_t stg = smBase + ASMKV + (t % 3) * ASTG;
#pragma unroll
        for (int it = 0; it < 2; it++) {
            int row = row0 + it * 32;
            size_t g = ((size_t)(b * S_ + t * 64 + row) * NKV_ + kvh) * HD_ + chunk * 8;
            uint32_t so = row * 128 + ((chunk ^ (row & 7)) * 16);
            cpasync16(stg + so,         g_kh + g);
            cpasync16(stg + 8192 + so,  g_vh + g);
            cpasync16(stg + 16384 + so, g_vl + g);
        }
        cpcommit();
    };

    const int tmax = 2 * qt + 1;
    issue_kv(0);
    if (tmax >= 1) issue_kv(1);

    __syncthreads();   // Q ready

    // ---- Q fragments ----
    const int a_r = lane & 15;
    const int a_c = (lane >> 4) & 1;
    uint32_t qf[4][4];
    {
        int R = warp * 16 + a_r;
#pragma unroll
        for (int ks = 0; ks < 4; ks++) {
            int chi = ks * 2 + a_c;
            ldsm4(qf[ks], smBase + R * 128 + ((chi ^ (R & 7)) * 16));
        }
    }

    const int b_r = ((lane >> 4) & 1) * 8 + (lane & 7);
    const int b_c = (lane >> 3) & 1;
    const int t_grp = lane >> 3, t_off = lane & 7;
    const int tkey = ((t_grp & 1) * 8) + t_off;
    const int tnc  = t_grp >> 1;

    float yacc[8][4];
#pragma unroll
    for (int nf = 0; nf < 8; nf++)
#pragma unroll
        for (int r = 0; r < 4; r++) yacc[nf][r] = 0.f;
    float m0 = -INFINITY, m1 = -INFINITY, l0 = 0.f, l1 = 0.f;

    const float c2 = 0.125f * 1.44269504f;   // scale * log2(e)
    const int r0q = qt * 128 + warp * 16 + (lane >> 2);
    const int warp_last = qt * 128 + warp * 16 + 15;

    for (int t = 0; t <= tmax; t++) {
        if (t + 1 <= tmax) cpwait<1>();
        else               cpwait<0>();
        __syncthreads();   // everyone done reading stage (t-1)%3; stage t ready
        if (t + 2 <= tmax) issue_kv(t + 2);   // safe: fills (t-1)%3 post-barrier

        const bool skip = warp_last < t * 64;
        if (!skip) {
            const uint32_t sK  = smBase + ASMKV + (t % 3) * ASTG;
            const uint32_t sV  = sK + 8192;
            const uint32_t sVl = sK + 16384;

            // ---- S = Q K^T (both single fp16) ----
            float s[8][4];
#pragma unroll
            for (int nf = 0; nf < 8; nf++)
#pragma unroll
                for (int r = 0; r < 4; r++) s[nf][r] = 0.f;

#pragma unroll
            for (int ks = 0; ks < 4; ks++) {
                uint32_t kb[8][2];
#pragma unroll
                for (int np = 0; np < 4; np++) {
                    int R = np * 16 + b_r;
                    int chi = ks * 2 + b_c;
                    uint32_t tt[4];
                    ldsm4(tt, sK + R * 128 + ((chi ^ (R & 7)) * 16));
                    kb[2 * np][0] = tt[0]; kb[2 * np][1] = tt[1];
                    kb[2 * np + 1][0] = tt[2]; kb[2 * np + 1][1] = tt[3];
                }
#pragma unroll
                for (int nf = 0; nf < 8; nf++)
                    mma16816h(s[nf], qf[ks], kb[nf]);
            }

            // ---- causal mask (only possible on last two tiles) ----
            if (t >= 2 * qt) {
#pragma unroll
                for (int nf = 0; nf < 8; nf++) {
                    int c0 = t * 64 + nf * 8 + (lane & 3) * 2;
                    if (c0 > r0q)          s[nf][0] = -INFINITY;
                    if (c0 + 1 > r0q)      s[nf][1] = -INFINITY;
                    if (c0 > r0q + 8)      s[nf][2] = -INFINITY;
                    if (c0 + 1 > r0q + 8)  s[nf][3] = -INFINITY;
                }
            }

            // ---- online softmax (base-2) ----
            float tm0 = -INFINITY, tm1 = -INFINITY;
#pragma unroll
            for (int nf = 0; nf < 8; nf++) {
                tm0 = fmaxf(tm0, fmaxf(s[nf][0], s[nf][1]));
                tm1 = fmaxf(tm1, fmaxf(s[nf][2], s[nf][3]));
            }
            tm0 = fmaxf(tm0, __shfl_xor_sync(0xffffffffu, tm0, 1));
            tm0 = fmaxf(tm0, __shfl_xor_sync(0xffffffffu, tm0, 2));
            tm1 = fmaxf(tm1, __shfl_xor_sync(0xffffffffu, tm1, 1));
            tm1 = fmaxf(tm1, __shfl_xor_sync(0xffffffffu, tm1, 2));

            float mn0 = fmaxf(m0, tm0), mn1 = fmaxf(m1, tm1);
            float mb0 = mn0 * c2, mb1 = mn1 * c2;
            float cr0 = exp2f(m0 * c2 - mb0);
            float cr1 = exp2f(m1 * c2 - mb1);
            l0 *= cr0; l1 *= cr1;
#pragma unroll
            for (int nf = 0; nf < 8; nf++) {
                yacc[nf][0] *= cr0; yacc[nf][1] *= cr0;
                yacc[nf][2] *= cr1; yacc[nf][3] *= cr1;
            }
#pragma unroll
            for (int nf = 0; nf < 8; nf++) {
                s[nf][0] = exp2f(fmaf(s[nf][0], c2, -mb0));
                s[nf][1] = exp2f(fmaf(s[nf][1], c2, -mb0));
                s[nf][2] = exp2f(fmaf(s[nf][2], c2, -mb1));
                s[nf][3] = exp2f(fmaf(s[nf][3], c2, -mb1));
                l0 += s[nf][0] + s[nf][1];
                l1 += s[nf][2] + s[nf][3];
            }
            m0 = mn0; m1 = mn1;

            // ---- y += P V  (P single fp16, V 2-term fp16) ----
#pragma unroll
            for (int ks = 0; ks < 4; ks++) {
                uint32_t ph[4];
                {
                    float* e = s[2 * ks];
                    float* o = s[2 * ks + 1];
                    ph[0] = packh2(e[0], e[1]); ph[1] = packh2(e[2], e[3]);
                    ph[2] = packh2(o[0], o[1]); ph[3] = packh2(o[2], o[3]);
                }
                int keyr = ks * 16 + tkey;
#pragma unroll
                for (int np = 0; np < 4; np++) {
                    int nch = np * 2 + tnc;
                    uint32_t vh[4], vl[4];
                    ldsm4t(vh, sV  + keyr * 128 + ((nch ^ (keyr & 7)) * 16));
                    ldsm4t(vl, sVl + keyr * 128 + ((nch ^ (keyr & 7)) * 16));
                    uint32_t bh0[2] = {vh[0], vh[1]}, bh1[2] = {vh[2], vh[3]};
                    uint32_t bl0[2] = {vl[0], vl[1]}, bl1[2] = {vl[2], vl[3]};
                    mma16816h(yacc[2 * np],     ph, bh0);
                    mma16816h(yacc[2 * np],     ph, bl0);
                    mma16816h(yacc[2 * np + 1], ph, bh1);
                    mma16816h(yacc[2 * np + 1], ph, bl1);
                }
            }
        }
    }

    // ---- finalize: normalize, store fp16 hi/lo y ----
    l0 += __shfl_xor_sync(0xffffffffu, l0, 1);
    l0 += __shfl_xor_sync(0xffffffffu, l0, 2);
    l1 += __shfl_xor_sync(0xffffffffu, l1, 1);
    l1 += __shfl_xor_sync(0xffffffffu, l1, 2);
    float inv0 = 1.f / l0, inv1 = 1.f / l1;

    int tok0 = b * S_ + qt * 128 + warp * 16 + (lane >> 2);
    int tok1 = tok0 + 8;
#pragma unroll
    for (int nf = 0; nf < 8; nf++) {
        int col = h * 64 + nf * 8 + (lane & 3) * 2;
        float y0 = yacc[nf][0] * inv0, y1 = yacc[nf][1] * inv0;
        float y2 = yacc[nf][2] * inv1, y3 = yacc[nf][3] * inv1;
        float h0 = __half2float(__float2half(y0));
        float h1 = __half2float(__float2half(y1));
        float h2 = __half2float(__float2half(y2));
        float h3 = __half2float(__float2half(y3));
        *(uint32_t*)(g_yh + (size_t)tok0 * E_ + col) = packh2(h0, h1);
        *(uint32_t*)(g_yl + (size_t)tok0 * E_ + col) = packh2(y0 - h0, y1 - h1);
        *(uint32_t*)(g_yh + (size_t)tok1 * E_ + col) = packh2(h2, h3);
        *(uint32_t*)(g_yl + (size_t)tok1 * E_ + col) = packh2(y2 - h2, y3 - h3);
    }
}

// ---------------------------------------------------------------------------
// launch — inputs: 0:x 1:ve 2:cos 3:sin 4:attn_mask 5:Wq 6:Wk 7:Wv 8:Wproj 9:Wgate
// ---------------------------------------------------------------------------
extern "C" void kernel_launch(void* const* d_in, const int* in_sizes, int n_in,
                              void* d_out, int out_size)
{
    (void)in_sizes; (void)n_in; (void)out_size;
    const float* x     = (const float*)d_in[0];
    const float* ve    = (const float*)d_in[1];
    const float* cosb  = (const float*)d_in[2];
    const float* sinb  = (const float*)d_in[3];
    const float* Wq    = (const float*)d_in[5];
    const float* Wk    = (const float*)d_in[6];
    const float* Wv    = (const float*)d_in[7];
    const float* Wproj = (const float*)d_in[8];
    const float* Wgate = (const float*)d_in[9];
    float* out = (float*)d_out;

    float* qkv;
    cudaGetSymbolAddress((void**)&qkv, g_qkv);
    __half *xh, *xl, *yh, *yl, *w;
    cudaGetSymbolAddress((void**)&xh, g_xh);
    cudaGetSymbolAddress((void**)&xl, g_xl);
    cudaGetSymbolAddress((void**)&yh, g_yh);
    cudaGetSymbolAddress((void**)&yl, g_yl);
    cudaGetSymbolAddress((void**)&w,  g_w);

    static int smem_set = 0;
    if (!smem_set) {
        cudaFuncSetAttribute(attn_mma_kernel,
                             cudaFuncAttributeMaxDynamicSharedMemorySize, ATT_SMEM);
        cudaFuncSetAttribute(gemm_h2,
                             cudaFuncAttributeMaxDynamicSharedMemorySize, GEMM_SMEM);
        smem_set = 1;
    }

    // splits (2 launches)
    {
        int n4 = TOKENS * E_ / 4;
        split_kernel<<<(n4 + 255) / 256, 256>>>(x, xh, xl, n4);
        int w4 = 2560 * E_ / 4;
        splitw_kernel<<<(w4 + 255) / 256, 256>>>(Wq, Wk, Wv, Wproj);
    }

    // fused QKV projection (fp16 2-term)
    {
        dim3 g(1536 / 128, TOKENS / 128);
        gemm_h2<<<g, 256, GEMM_SMEM>>>(xh, xl, w, qkv, TOKENS, 1536, E_);
    }

    // gate + ve, rope + rmsnorm (emits fp16 q, k single; v hi/lo)
    ew_kernel<<<TOKENS, 256>>>(x, ve, cosb, sinb, Wgate);

    // fp16 tensor-core flash attention (emits fp16 hi/lo y)
    {
        dim3 ga(S_ / 128, B_ * NH_);
        attn_mma_kernel<<<ga, 256, ATT_SMEM>>>();
    }

    // output projection (fp16 2-term)
    {
        dim3 gp(E_ / 128, TOKENS / 128);
        gemm_h2<<<gp, 256, GEMM_SMEM>>>(yh, yl, w + WP_OFF, out, TOKENS, E_, E_);
    }
}